// round 10
// baseline (speedup 1.0000x reference)
#include <cuda_runtime.h>

#define NN 131072
#define DD 64
#define KK 512
#define ITERS 5
#define MROWS 128
#define NCHUNKS 4

#define FP_SCALE 1099511627776.0f          // 2^40
#define FP_INV   (1.0 / 1099511627776.0)   // 2^-40

// ---- smem layout (dynamic) ----
#define SM_A     0            // 64KB: A hi/lo frag-layout [mt8][h2][s8][lane32][4f]
#define SM_B     65536        // 2 x 64KB: B bufs [nt16][h2][s8][lane32][2f]
#define SM_C2    196608       // 512 f
#define SM_RB1   198656       // [2][128] f
#define SM_RB2   199680
#define SM_RI1   200704
#define SM_RI2   201728
#define SM_BIDX  202752       // [128] i
#define SMEM_REQ 203264

// ---------------- scratch (device globals; no allocation allowed) ----------
__device__ __align__(256) float g_centers[KK * DD];
__device__ float g_c2[KK];
__device__ __align__(256) unsigned long long g_isums[KK * DD];
__device__ int   g_icounts[KK];
__device__ int   g_assign[NN];

// ---------------- helpers ----------------------------------------------------
__device__ __forceinline__ unsigned smem_u32(const void* p) {
    unsigned a;
    asm("{ .reg .u64 t; cvta.to.shared.u64 t, %1; cvt.u32.u64 %0, t; }"
        : "=r"(a) : "l"(p));
    return a;
}
__device__ __forceinline__ unsigned to_tf32(float x) {
    unsigned u;
    asm("cvt.rna.tf32.f32 %0, %1;" : "=r"(u) : "f"(x));
    return u;
}
__device__ __forceinline__ void sts128(unsigned a, unsigned x, unsigned y,
                                       unsigned z, unsigned w) {
    asm volatile("st.shared.v4.b32 [%0], {%1,%2,%3,%4};"
                 :: "r"(a), "r"(x), "r"(y), "r"(z), "r"(w) : "memory");
}
__device__ __forceinline__ void sts64(unsigned a, unsigned x, unsigned y) {
    asm volatile("st.shared.v2.b32 [%0], {%1,%2};"
                 :: "r"(a), "r"(x), "r"(y) : "memory");
}
__device__ __forceinline__ void stsf32(unsigned a, float v) {
    asm volatile("st.shared.f32 [%0], %1;" :: "r"(a), "f"(v) : "memory");
}
__device__ __forceinline__ void stsi32(unsigned a, int v) {
    asm volatile("st.shared.b32 [%0], %1;" :: "r"(a), "r"(v) : "memory");
}
__device__ __forceinline__ float ldsf32(unsigned a) {
    float v; asm("ld.shared.f32 %0, [%1];" : "=f"(v) : "r"(a)); return v;
}
__device__ __forceinline__ int ldsi32(unsigned a) {
    int v; asm("ld.shared.b32 %0, [%1];" : "=r"(v) : "r"(a)); return v;
}
__device__ __forceinline__ uint4 lds128(unsigned a) {
    uint4 v;
    asm("ld.shared.v4.b32 {%0,%1,%2,%3}, [%4];"
        : "=r"(v.x), "=r"(v.y), "=r"(v.z), "=r"(v.w) : "r"(a));
    return v;
}
__device__ __forceinline__ uint2 lds64(unsigned a) {
    uint2 v;
    asm("ld.shared.v2.b32 {%0,%1}, [%2];" : "=r"(v.x), "=r"(v.y) : "r"(a));
    return v;
}
__device__ __forceinline__ float2 lds_f2(unsigned a) {
    float2 v;
    asm("ld.shared.v2.f32 {%0,%1}, [%2];" : "=f"(v.x), "=f"(v.y) : "r"(a));
    return v;
}
__device__ __forceinline__ void red_add_u64(unsigned long long* p, unsigned long long v) {
    asm volatile("red.global.add.u64 [%0], %1;\n" :: "l"(p), "l"(v) : "memory");
}
// tf32 tensor-core mma (PTX ISA sm_80+, valid on plain sm_103)
__device__ __forceinline__ void mma_tf32(float* c, uint4 a, uint2 b) {
    asm volatile(
        "mma.sync.aligned.m16n8k8.row.col.f32.tf32.tf32.f32 "
        "{%0,%1,%2,%3}, {%4,%5,%6,%7}, {%8,%9}, {%0,%1,%2,%3};"
        : "+f"(c[0]), "+f"(c[1]), "+f"(c[2]), "+f"(c[3])
        : "r"(a.x), "r"(a.y), "r"(a.z), "r"(a.w), "r"(b.x), "r"(b.y));
}
__device__ __forceinline__ void top2_update(float& b1, int& i1, float& b2, int& i2,
                                            float m, int idx) {
    if (m < b1)      { b2 = b1; i2 = i1; b1 = m; i1 = idx; }
    else if (m < b2) { b2 = m;  i2 = idx; }
}
__device__ __forceinline__ float metric_exact(const float* x, const float* cen,
                                              float c2v) {
    float dot = 0.0f;
    #pragma unroll
    for (int d = 0; d < DD; d++) dot = __fmaf_rn(x[d], cen[d], dot);
    return __fsub_rn(c2v, __fmul_rn(2.0f, dot));
}

// ---------------- prep: zero sums/counts, c2 of initial centers ------------
__global__ void prep_kernel(const float* __restrict__ centers0) {
    int k = blockIdx.x;
    int d = threadIdx.x;
    float v = centers0[k * DD + d];
    g_isums[k * DD + d] = 0ULL;
    if (d == 0) g_icounts[k] = 0;

    float s = __fmul_rn(v, v);
    #pragma unroll
    for (int o = 16; o > 0; o >>= 1) s += __shfl_down_sync(0xffffffffu, s, o);
    __shared__ float sh[2];
    if ((d & 31) == 0) sh[d >> 5] = s;
    __syncthreads();
    if (d == 0) g_c2[k] = __fadd_rn(sh[0], sh[1]);
}

// ---------------- assign: tf32 split GEMM on tensor cores -------------------
__global__ __launch_bounds__(256) void assign_kernel(
    const float* __restrict__ X,
    const float* __restrict__ centers0,
    int iter)
{
    const float* __restrict__ C = (iter == 0) ? centers0 : g_centers;

    extern __shared__ __align__(16) char smem_raw[];
    const unsigned base = smem_u32(smem_raw);
    const unsigned Ab  = base + SM_A;
    const unsigned Bb  = base + SM_B;
    const unsigned C2b = base + SM_C2;

    const int tid = threadIdx.x;
    const int l = tid & 31, w = tid >> 5;
    const int wm = w & 3, wn = w >> 2;
    const int g = l >> 2, q = l & 3;

    // c2 -> smem
    #pragma unroll
    for (int i = 0; i < 2; i++)
        stsf32(C2b + (tid + i * 256) * 4, g_c2[tid + i * 256]);

    const float* Xg = X + (size_t)blockIdx.x * MROWS * DD;

    // ---- stage A: warp w covers kstep s=w; per-lane 16B chunks ----
    {
        const int k = 8 * w + q;
        #pragma unroll
        for (int mt = 0; mt < 8; mt++) {
            const int r0 = mt * 16 + g;
            float x00 = Xg[r0 * DD + k];
            float x10 = Xg[(r0 + 8) * DD + k];
            float x01 = Xg[r0 * DD + k + 4];
            float x11 = Xg[(r0 + 8) * DD + k + 4];
            unsigned h00 = to_tf32(x00), h10 = to_tf32(x10);
            unsigned h01 = to_tf32(x01), h11 = to_tf32(x11);
            unsigned o00 = to_tf32(x00 - __uint_as_float(h00));
            unsigned o10 = to_tf32(x10 - __uint_as_float(h10));
            unsigned o01 = to_tf32(x01 - __uint_as_float(h01));
            unsigned o11 = to_tf32(x11 - __uint_as_float(h11));
            sts128(Ab + mt * 8192 + w * 512 + l * 16, h00, h10, h01, h11);
            sts128(Ab + mt * 8192 + 4096 + w * 512 + l * 16, o00, o10, o01, o11);
        }
    }
    // ---- stage B chunk 0 ----
    {
        #pragma unroll
        for (int nt = 0; nt < 16; nt++) {
            int gc = nt * 8 + g;
            float v0 = C[gc * DD + 8 * w + q];
            float v1 = C[gc * DD + 8 * w + q + 4];
            unsigned h0 = to_tf32(v0), h1 = to_tf32(v1);
            unsigned o0 = to_tf32(v0 - __uint_as_float(h0));
            unsigned o1 = to_tf32(v1 - __uint_as_float(h1));
            sts64(Bb + nt * 4096 + w * 256 + l * 8, h0, h1);
            sts64(Bb + nt * 4096 + 2048 + w * 256 + l * 8, o0, o1);
        }
    }
    __syncthreads();

    float b1v[2][2], b2v[2][2];
    int   i1v[2][2], i2v[2][2];
    #pragma unroll
    for (int mi = 0; mi < 2; mi++)
        #pragma unroll
        for (int u = 0; u < 2; u++) {
            b1v[mi][u] = 3.4e38f; b2v[mi][u] = 3.4e38f;
            i1v[mi][u] = 0;       i2v[mi][u] = 0;
        }

    for (int c = 0; c < NCHUNKS; c++) {
        // prefetch next chunk's B values (globals) into regs
        float pv0[16], pv1[16];
        if (c + 1 < NCHUNKS) {
            #pragma unroll
            for (int nt = 0; nt < 16; nt++) {
                int gc = (c + 1) * 128 + nt * 8 + g;
                pv0[nt] = C[gc * DD + 8 * w + q];
                pv1[nt] = C[gc * DD + 8 * w + q + 4];
            }
        }
        const unsigned bufb = Bb + (unsigned)(c & 1) * 65536u;

        float acc[2][8][4];
        #pragma unroll
        for (int mi = 0; mi < 2; mi++)
            #pragma unroll
            for (int nt = 0; nt < 8; nt++)
                #pragma unroll
                for (int j = 0; j < 4; j++) acc[mi][nt][j] = 0.0f;

        // 4 split-products x 8 ksteps
        #pragma unroll
        for (int combo = 0; combo < 4; combo++) {
            const int ha = combo >> 1, hb = combo & 1;
            #pragma unroll
            for (int s = 0; s < 8; s++) {
                uint4 af[2];
                #pragma unroll
                for (int mi = 0; mi < 2; mi++)
                    af[mi] = lds128(Ab + (2 * wm + mi) * 8192 + ha * 4096
                                    + s * 512 + l * 16);
                uint2 bf[8];
                #pragma unroll
                for (int nt = 0; nt < 8; nt++)
                    bf[nt] = lds64(bufb + (8 * wn + nt) * 4096 + hb * 2048
                                   + s * 256 + l * 8);
                #pragma unroll
                for (int mi = 0; mi < 2; mi++)
                    #pragma unroll
                    for (int nt = 0; nt < 8; nt++)
                        mma_tf32(acc[mi][nt], af[mi], bf[nt]);
            }
        }

        // candidates: metric = c2 - 2*dot (x2 constant per row)
        #pragma unroll
        for (int nt = 0; nt < 8; nt++) {
            const int colb = c * 128 + (8 * wn + nt) * 8 + 2 * q;
            float2 cc = lds_f2(C2b + colb * 4);
            #pragma unroll
            for (int mi = 0; mi < 2; mi++)
                #pragma unroll
                for (int u = 0; u < 2; u++) {
                    float m0 = __fsub_rn(cc.x, __fmul_rn(2.0f, acc[mi][nt][u * 2 + 0]));
                    float m1 = __fsub_rn(cc.y, __fmul_rn(2.0f, acc[mi][nt][u * 2 + 1]));
                    top2_update(b1v[mi][u], i1v[mi][u], b2v[mi][u], i2v[mi][u], m0, colb);
                    top2_update(b1v[mi][u], i1v[mi][u], b2v[mi][u], i2v[mi][u], m1, colb + 1);
                }
        }
        __syncthreads();

        if (c + 1 < NCHUNKS) {
            const unsigned nb = Bb + (unsigned)((c + 1) & 1) * 65536u;
            #pragma unroll
            for (int nt = 0; nt < 16; nt++) {
                unsigned h0 = to_tf32(pv0[nt]), h1 = to_tf32(pv1[nt]);
                unsigned o0 = to_tf32(pv0[nt] - __uint_as_float(h0));
                unsigned o1 = to_tf32(pv1[nt] - __uint_as_float(h1));
                sts64(nb + nt * 4096 + w * 256 + l * 8, h0, h1);
                sts64(nb + nt * 4096 + 2048 + w * 256 + l * 8, o0, o1);
            }
            __syncthreads();
        }
    }

    // ---- cross-lane top2 merge within 4-lane groups (same rows) ----
    #pragma unroll
    for (int mi = 0; mi < 2; mi++)
        #pragma unroll
        for (int u = 0; u < 2; u++) {
            float B1 = b1v[mi][u], B2 = b2v[mi][u];
            int   I1 = i1v[mi][u], I2 = i2v[mi][u];
            #pragma unroll
            for (int off = 1; off <= 2; off <<= 1) {
                float oB1 = __shfl_xor_sync(0xffffffffu, B1, off);
                int   oI1 = __shfl_xor_sync(0xffffffffu, I1, off);
                float oB2 = __shfl_xor_sync(0xffffffffu, B2, off);
                int   oI2 = __shfl_xor_sync(0xffffffffu, I2, off);
                if (oB1 < B1 || (oB1 == B1 && oI1 < I1)) {
                    if (B1 < oB2 || (B1 == oB2 && I1 < oI2)) { B2 = B1; I2 = I1; }
                    else { B2 = oB2; I2 = oI2; }
                    B1 = oB1; I1 = oI1;
                } else {
                    if (oB1 < B2) { B2 = oB1; I2 = oI1; }
                }
            }
            if (q == 0) {
                int row = (2 * wm + mi) * 16 + u * 8 + g;
                stsf32(base + SM_RB1 + (wn * 128 + row) * 4, B1);
                stsf32(base + SM_RB2 + (wn * 128 + row) * 4, B2);
                stsi32(base + SM_RI1 + (wn * 128 + row) * 4, I1);
                stsi32(base + SM_RI2 + (wn * 128 + row) * 4, I2);
            }
        }
    __syncthreads();

    // ---- per-row final merge + near-tie exact refine ----
    if (tid < MROWS) {
        int row = tid;
        float B1 = ldsf32(base + SM_RB1 + row * 4);
        float B2 = ldsf32(base + SM_RB2 + row * 4);
        int   I1 = ldsi32(base + SM_RI1 + row * 4);
        int   I2 = ldsi32(base + SM_RI2 + row * 4);
        float oB1 = ldsf32(base + SM_RB1 + (128 + row) * 4);
        float oB2 = ldsf32(base + SM_RB2 + (128 + row) * 4);
        int   oI1 = ldsi32(base + SM_RI1 + (128 + row) * 4);
        int   oI2 = ldsi32(base + SM_RI2 + (128 + row) * 4);
        if (oB1 < B1) {           // ties keep wn=0 (lower cols)
            if (B1 < oB2) { B2 = B1; I2 = I1; }
            else          { B2 = oB2; I2 = oI2; }
            B1 = oB1; I1 = oI1;
        } else {
            if (oB1 < B2) { B2 = oB1; I2 = oI1; }
        }

        int bi = I1;
        if (B2 - B1 < 1e-3f) {    // near-tie: resolve with exact fp32
            const float* xr = Xg + row * DD;
            float mA = metric_exact(xr, C + (size_t)I1 * DD, ldsf32(C2b + I1 * 4));
            float mB = metric_exact(xr, C + (size_t)I2 * DD, ldsf32(C2b + I2 * 4));
            if (mB < mA || (mB == mA && I2 < I1)) bi = I2;
        }
        stsi32(base + SM_BIDX + row * 4, bi);
        g_assign[blockIdx.x * MROWS + row] = bi;
        atomicAdd(&g_icounts[bi], 1);
    }
    __syncthreads();

    // ---- deterministic fixed-point sums (2 threads/row) ----
    {
        int row = tid >> 1, half = tid & 1;
        int bi = ldsi32(base + SM_BIDX + row * 4);
        const float4* xr = (const float4*)(Xg + row * DD + half * 32);
        unsigned long long* s = &g_isums[(size_t)bi * DD + half * 32];
        #pragma unroll
        for (int qq = 0; qq < 8; qq++) {
            float4 v = xr[qq];
            red_add_u64(&s[qq * 4 + 0], (unsigned long long)llrintf(v.x * FP_SCALE));
            red_add_u64(&s[qq * 4 + 1], (unsigned long long)llrintf(v.y * FP_SCALE));
            red_add_u64(&s[qq * 4 + 2], (unsigned long long)llrintf(v.z * FP_SCALE));
            red_add_u64(&s[qq * 4 + 3], (unsigned long long)llrintf(v.w * FP_SCALE));
        }
    }
}

// ---------------- centers update (+ c2, + reset sums/counts) ---------------
__global__ void update_kernel(const float* __restrict__ X,
                              const int* __restrict__ repl,
                              int iter)
{
    int k = blockIdx.x;
    int d = threadIdx.x;
    int icnt = g_icounts[k];
    long long ll = (long long)g_isums[k * DD + d];
    float s   = (float)((double)ll * FP_INV);
    float cnt = (float)icnt;
    float v   = __fdiv_rn(s, fmaxf(cnt, 1.0f));
    if (v == 0.0f) {
        int r = repl[iter * KK + k];
        v = X[(size_t)r * DD + d];
    }
    g_centers[k * DD + d] = v;
    g_isums[k * DD + d] = 0ULL;
    if (d == 0) g_icounts[k] = 0;

    float sq = __fmul_rn(v, v);
    #pragma unroll
    for (int o = 16; o > 0; o >>= 1) sq += __shfl_down_sync(0xffffffffu, sq, o);
    __shared__ float sh[2];
    if ((d & 31) == 0) sh[d >> 5] = sq;
    __syncthreads();
    if (d == 0) g_c2[k] = __fadd_rn(sh[0], sh[1]);
}

// ---------------- output: [assignments as float | centers] -----------------
__global__ void out_kernel(float* __restrict__ out) {
    int i = blockIdx.x * blockDim.x + threadIdx.x;
    if (i < NN) {
        out[i] = (float)g_assign[i];
    } else if (i < NN + KK * DD) {
        out[i] = g_centers[i - NN];
    }
}

// ---------------- launch ----------------------------------------------------
extern "C" void kernel_launch(void* const* d_in, const int* in_sizes, int n_in,
                              void* d_out, int out_size)
{
    const float* X    = nullptr;
    const float* C0   = nullptr;
    const int*   repl = nullptr;
    for (int i = 0; i < n_in; i++) {
        if (in_sizes[i] == NN * DD)       X    = (const float*)d_in[i];
        else if (in_sizes[i] == KK * DD)  C0   = (const float*)d_in[i];
        else if (in_sizes[i] == ITERS*KK) repl = (const int*)d_in[i];
    }
    float* out = (float*)d_out;

    cudaFuncSetAttribute(assign_kernel,
                         cudaFuncAttributeMaxDynamicSharedMemorySize, SMEM_REQ);

    prep_kernel<<<KK, DD>>>(C0);
    for (int i = 0; i < ITERS; i++) {
        assign_kernel<<<NN / MROWS, 256, SMEM_REQ>>>(X, C0, i);
        update_kernel<<<KK, DD>>>(X, repl, i);
    }
    int total = NN + KK * DD;
    out_kernel<<<(total + 255) / 256, 256>>>(out);
}